// round 4
// baseline (speedup 1.0000x reference)
#include <cuda_runtime.h>
#include <math.h>
#include <stdint.h>

#define T   2048
#define H   1024
#define FF  3584
#define NE  8
#define TK  2
#define NSLOT (T*TK)

#define BM  128
#define BK  32
#define SMEMSZ (65536 + 1024)

// ---- scratch (device globals; no runtime allocation allowed) ----
__device__ __align__(16) float d_act[(size_t)(NSLOT + BM) * FF];
__device__ __align__(16) float d_y[(size_t)NSLOT * H];
__device__ int   d_slot_token[NSLOT];
__device__ float d_slot_w[NSLOT];
__device__ int   d_token_slot[NSLOT];
__device__ int   d_topk_e[NSLOT];
__device__ float d_topk_w[NSLOT];
__device__ int   d_counts[NE];
__device__ int   d_offsets[NE];
__device__ int   d_cursor[NE];

// ===================== helpers =====================
__device__ __forceinline__ uint32_t f2tf(float f) {
    uint32_t r;
    asm("cvt.rna.tf32.f32 %0, %1;" : "=r"(r) : "f"(f));
    return r;
}
__device__ __forceinline__ void mma_tf32(float* c, uint32_t a0, uint32_t a1,
                                         uint32_t a2, uint32_t a3,
                                         uint32_t b0, uint32_t b1) {
    asm volatile(
        "mma.sync.aligned.m16n8k8.row.col.f32.tf32.tf32.f32 "
        "{%0,%1,%2,%3}, {%4,%5,%6,%7}, {%8,%9}, {%0,%1,%2,%3};\n"
        : "+f"(c[0]), "+f"(c[1]), "+f"(c[2]), "+f"(c[3])
        : "r"(a0), "r"(a1), "r"(a2), "r"(a3), "r"(b0), "r"(b1));
}
__device__ __forceinline__ uint4 lds128(const char* p) {
    return *(const uint4*)p;
}

// ===================== small kernels =====================
__global__ void zero_counts_kernel() {
    if (threadIdx.x < NE) d_counts[threadIdx.x] = 0;
}

__global__ void router_kernel(const float* __restrict__ x,
                              const float* __restrict__ gw,
                              float* __restrict__ logits, int write_logits)
{
    int warp = (blockIdx.x * blockDim.x + threadIdx.x) >> 5;
    int lane = threadIdx.x & 31;
    if (warp >= T) return;
    const float* xr = x + (size_t)warp * H;

    float acc[NE];
#pragma unroll
    for (int e = 0; e < NE; e++) acc[e] = 0.f;
    for (int i = lane; i < H; i += 32) {
        float xv = xr[i];
#pragma unroll
        for (int e = 0; e < NE; e++) acc[e] += xv * gw[e * H + i];
    }
#pragma unroll
    for (int e = 0; e < NE; e++) {
#pragma unroll
        for (int off = 16; off > 0; off >>= 1)
            acc[e] += __shfl_xor_sync(0xffffffffu, acc[e], off);
    }
    if (lane == 0) {
        if (write_logits) {
#pragma unroll
            for (int e = 0; e < NE; e++) logits[warp * NE + e] = acc[e];
        }
        int i0 = 0;
#pragma unroll
        for (int e = 1; e < NE; e++) if (acc[e] > acc[i0]) i0 = e;
        int i1 = (i0 == 0) ? 1 : 0;
#pragma unroll
        for (int e = 0; e < NE; e++)
            if (e != i0 && acc[e] > acc[i1]) i1 = e;
        float m  = fmaxf(acc[i0], acc[i1]);
        float p0 = expf(acc[i0] - m), p1 = expf(acc[i1] - m);
        float inv = 1.f / (p0 + p1);
        d_topk_e[warp * 2 + 0] = i0;  d_topk_w[warp * 2 + 0] = p0 * inv;
        d_topk_e[warp * 2 + 1] = i1;  d_topk_w[warp * 2 + 1] = p1 * inv;
        atomicAdd(&d_counts[i0], 1);
        atomicAdd(&d_counts[i1], 1);
    }
}

__global__ void scan_kernel() {
    int off = 0;
    for (int e = 0; e < NE; e++) {
        d_offsets[e] = off;
        off += d_counts[e];
        d_cursor[e] = 0;
    }
}

__global__ void scatter_kernel() {
    int t = blockIdx.x * blockDim.x + threadIdx.x;
    if (t >= T) return;
#pragma unroll
    for (int k = 0; k < TK; k++) {
        int e   = d_topk_e[t * 2 + k];
        int pos = d_offsets[e] + atomicAdd(&d_cursor[e], 1);
        d_slot_token[pos]       = t;
        d_slot_w[pos]           = d_topk_w[t * 2 + k];
        d_token_slot[t * 2 + k] = pos;
    }
}

// ===================== fragment-major mma.sync GEMM =====================
// SMEM stage layout (per 128m x 32k A tile): 32 groups (tm*4+tk) of
// [lane 0..31][4 regs], reg order (m_lo,k_lo)(m_lo,k_hi)(m_hi,k_lo)(m_hi,k_hi).
// B (32k x 128n): 32 groups (tn*2+tkp) of [lane][4 regs], reg i = W[k+4i][n].
// Consumer fragment = single LDS.128 at  base + group*512 + lane*16.
//
// IS1: tile 128m x (64 gate | 64 up), warps 4m x 2n, warp 32m x (32g+32u)
//      epilogue silu(g)*u*routing_w -> d_act
// !IS1: tile 128m x 128n, warps 2m x 4n, warp 64m x 32n -> d_y
template <int KTOT, bool IS1>
__global__ __launch_bounds__(256)
void moe_gemm_mma(const float* __restrict__ Aglob, const float* __restrict__ Wg)
{
    constexpr int NB = IS1 ? (2 * FF) : H;
    constexpr int NI = KTOT / BK;
    constexpr int STAGE = 32768;

    int e   = blockIdx.z;
    int cnt = d_counts[e];
    int m0  = blockIdx.x * BM;
    if (m0 >= cnt) return;
    int seg = d_offsets[e];

    extern __shared__ __align__(16) char smem[];
    int* stok = (int*)(smem + 65536);

    int t = threadIdx.x, w = t >> 5, lane = t & 31;
    int g = lane >> 2, tig = lane & 3;

    // token table (gemm1 gather)
    if (IS1) {
        if (t < BM) {
            int m = m0 + t;
            stok[t] = d_slot_token[seg + (m < cnt ? m : cnt - 1)];
        }
        __syncthreads();
    }

    // ---------- producer setup: 4 A slots + 4 B slots per thread ----------
    const float* pA[4][2];
    const float* pB[4];
#pragma unroll
    for (int j = 0; j < 4; j++) {
        int grp = w + 8 * j;
        // A slot
        int tm = grp >> 2, tk = grp & 3;
        int mlo = tm * 16 + g;
        int kb  = tk * 8 + tig;
        if (IS1) {
            pA[j][0] = Aglob + (size_t)stok[mlo] * KTOT + kb;
            pA[j][1] = Aglob + (size_t)stok[mlo + 8] * KTOT + kb;
        } else {
            pA[j][0] = d_act + (size_t)(seg + m0 + mlo) * KTOT + kb;
            pA[j][1] = d_act + (size_t)(seg + m0 + mlo + 8) * KTOT + kb;
        }
        // B slot
        int tn = grp >> 1, tkp = grp & 1;
        int gcol;
        if (IS1) gcol = (tn < 8) ? (blockIdx.y * 64 + tn * 8 + g)
                                 : (FF + blockIdx.y * 64 + (tn - 8) * 8 + g);
        else     gcol = blockIdx.y * 128 + tn * 8 + g;
        pB[j] = Wg + (size_t)e * KTOT * NB + (size_t)(tkp * 16 + tig) * NB + gcol;
    }
    uint32_t sta[4], stb[4];
#pragma unroll
    for (int j = 0; j < 4; j++) {
        sta[j] = (uint32_t)((w + 8 * j) * 512 + lane * 16);
        stb[j] = 16384u + sta[j];
    }

    // ---------- consumer setup ----------
    constexpr int MT    = IS1 ? 2 : 4;
    constexpr int NSETS = IS1 ? 2 : 1;
    int mw = IS1 ? (w >> 1) : (w >> 2);
    int nw = IS1 ? (w & 1)  : (w & 3);

    uint32_t abase[MT];
#pragma unroll
    for (int mt = 0; mt < MT; mt++)
        abase[mt] = (uint32_t)(((mw * MT + mt) * 4) * 512 + lane * 16);
    uint32_t bbase[NSETS][4];
#pragma unroll
    for (int s = 0; s < NSETS; s++)
#pragma unroll
        for (int nt = 0; nt < 4; nt++) {
            int tn = s * 8 + nw * 4 + nt;
            bbase[s][nt] = (uint32_t)(16384 + (tn * 2) * 512 + lane * 16);
        }

    float acc[NSETS][MT][4][4];
#pragma unroll
    for (int s = 0; s < NSETS; s++)
#pragma unroll
        for (int mt = 0; mt < MT; mt++)
#pragma unroll
            for (int nt = 0; nt < 4; nt++)
#pragma unroll
                for (int q = 0; q < 4; q++) acc[s][mt][nt][q] = 0.f;

    // ---------- pipeline ----------
    float av[4][4], bv[4][4];
#pragma unroll
    for (int j = 0; j < 4; j++) {
        av[j][0] = __ldg(pA[j][0]);     av[j][1] = __ldg(pA[j][0] + 4);
        av[j][2] = __ldg(pA[j][1]);     av[j][3] = __ldg(pA[j][1] + 4);
#pragma unroll
        for (int i = 0; i < 4; i++) bv[j][i] = __ldg(pB[j] + (size_t)(4 * i) * NB);
    }

    for (int it = 0; it < NI; it++) {
        uint32_t sb = (it & 1) ? (uint32_t)STAGE : 0u;
        // store staged regs (convert to tf32)
#pragma unroll
        for (int j = 0; j < 4; j++) {
            *(uint4*)(smem + sb + sta[j]) =
                make_uint4(f2tf(av[j][0]), f2tf(av[j][1]), f2tf(av[j][2]), f2tf(av[j][3]));
            *(uint4*)(smem + sb + stb[j]) =
                make_uint4(f2tf(bv[j][0]), f2tf(bv[j][1]), f2tf(bv[j][2]), f2tf(bv[j][3]));
        }
        __syncthreads();
        // prefetch next chunk
        if (it + 1 < NI) {
            int k0 = (it + 1) * BK;
#pragma unroll
            for (int j = 0; j < 4; j++) {
                av[j][0] = __ldg(pA[j][0] + k0);     av[j][1] = __ldg(pA[j][0] + k0 + 4);
                av[j][2] = __ldg(pA[j][1] + k0);     av[j][3] = __ldg(pA[j][1] + k0 + 4);
#pragma unroll
                for (int i = 0; i < 4; i++)
                    bv[j][i] = __ldg(pB[j] + (size_t)(k0 + 4 * i) * NB);
            }
        }
        // compute from this buffer
        const char* sm = smem + sb;
        uint4 bfr[NSETS][4];
#pragma unroll
        for (int ks = 0; ks < 4; ks++) {
            if ((ks & 1) == 0) {
                uint32_t tkpoff = (uint32_t)((ks >> 1) * 512);
#pragma unroll
                for (int s = 0; s < NSETS; s++)
#pragma unroll
                    for (int nt = 0; nt < 4; nt++)
                        bfr[s][nt] = lds128(sm + bbase[s][nt] + tkpoff);
            }
#pragma unroll
            for (int mt = 0; mt < MT; mt++) {
                uint4 af = lds128(sm + abase[mt] + (uint32_t)(ks * 512));
#pragma unroll
                for (int s = 0; s < NSETS; s++)
#pragma unroll
                    for (int nt = 0; nt < 4; nt++) {
                        uint32_t b0 = (ks & 1) ? bfr[s][nt].z : bfr[s][nt].x;
                        uint32_t b1 = (ks & 1) ? bfr[s][nt].w : bfr[s][nt].y;
                        mma_tf32(acc[s][mt][nt], af.x, af.z, af.y, af.w, b0, b1);
                    }
            }
        }
        __syncthreads();
    }

    // ---------- epilogue ----------
    if (IS1) {
        int n0 = blockIdx.y * 64 + nw * 32;
#pragma unroll
        for (int mt = 0; mt < MT; mt++) {
#pragma unroll
            for (int rs = 0; rs < 2; rs++) {
                int m = m0 + mw * 32 + mt * 16 + g + rs * 8;
                if (m < cnt) {
                    int slot = seg + m;
                    float wgt = d_slot_w[slot];
                    float* row = d_act + (size_t)slot * FF + n0;
#pragma unroll
                    for (int nt = 0; nt < 4; nt++) {
                        float gv0 = acc[0][mt][nt][rs * 2 + 0];
                        float gv1 = acc[0][mt][nt][rs * 2 + 1];
                        float uv0 = acc[1][mt][nt][rs * 2 + 0];
                        float uv1 = acc[1][mt][nt][rs * 2 + 1];
                        float2 o;
                        o.x = gv0 / (1.f + expf(-gv0)) * uv0 * wgt;
                        o.y = gv1 / (1.f + expf(-gv1)) * uv1 * wgt;
                        *(float2*)(row + nt * 8 + 2 * tig) = o;
                    }
                }
            }
        }
    } else {
        int n0 = blockIdx.y * 128 + nw * 32;
#pragma unroll
        for (int mt = 0; mt < MT; mt++) {
#pragma unroll
            for (int rs = 0; rs < 2; rs++) {
                int m = m0 + mw * 64 + mt * 16 + g + rs * 8;
                if (m < cnt) {
                    int slot = seg + m;
                    float* row = d_y + (size_t)slot * H + n0;
#pragma unroll
                    for (int nt = 0; nt < 4; nt++) {
                        float2 o;
                        o.x = acc[0][mt][nt][rs * 2 + 0];
                        o.y = acc[0][mt][nt][rs * 2 + 1];
                        *(float2*)(row + nt * 8 + 2 * tig) = o;
                    }
                }
            }
        }
    }
}

// out[t, n] = y[slot0(t), n] + y[slot1(t), n]
__global__ void combine_kernel(float* __restrict__ out)
{
    int idx = blockIdx.x * blockDim.x + threadIdx.x;
    if (idx >= T * H) return;
    int t = idx >> 10;
    int n = idx & (H - 1);
    int s0 = d_token_slot[t * 2 + 0];
    int s1 = d_token_slot[t * 2 + 1];
    out[idx] = d_y[(size_t)s0 * H + n] + d_y[(size_t)s1 * H + n];
}

// ===================== launch =====================
extern "C" void kernel_launch(void* const* d_in, const int* in_sizes, int n_in,
                              void* d_out, int out_size)
{
    const float* x   = (const float*)d_in[0];   // [2,1024,1024]
    const float* gw  = (const float*)d_in[1];   // [8,1024]
    const float* wgu = (const float*)d_in[2];   // [8,1024,7168]
    const float* wdn = (const float*)d_in[3];   // [8,3584,1024]
    float* out = (float*)d_out;

    int write_logits = (out_size >= T * H + T * NE) ? 1 : 0;
    float* logits = out + (size_t)T * H;

    cudaFuncSetAttribute(moe_gemm_mma<H, true>,
                         cudaFuncAttributeMaxDynamicSharedMemorySize, SMEMSZ);
    cudaFuncSetAttribute(moe_gemm_mma<FF, false>,
                         cudaFuncAttributeMaxDynamicSharedMemorySize, SMEMSZ);

    zero_counts_kernel<<<1, 32>>>();
    router_kernel<<<(T * 32 + 255) / 256, 256>>>(x, gw, logits, write_logits);
    scan_kernel<<<1, 1>>>();
    scatter_kernel<<<(T + 255) / 256, 256>>>();
    moe_gemm_mma<H, true><<<dim3(16, FF / 64, NE), 256, SMEMSZ>>>(x, wgu);      // (16, 56, 8)
    moe_gemm_mma<FF, false><<<dim3(16, H / 128, NE), 256, SMEMSZ>>>(nullptr, wdn); // (16, 8, 8)
    combine_kernel<<<(T * H + 255) / 256, 256>>>(out);
}

// round 6
// speedup vs baseline: 1.3889x; 1.3889x over previous
#include <cuda_runtime.h>
#include <math.h>
#include <stdint.h>

#define T   2048
#define H   1024
#define FF  3584
#define NE  8
#define TK  2
#define NSLOT (T*TK)

#define BM   128
#define BK   32
#define NI1  (H / BK)    // 32
#define NI2  (FF / BK)   // 112
#define SMEMSZ 65536

// ---- scratch (device globals; no runtime allocation allowed) ----
__device__ __align__(16) float d_act[(size_t)(NSLOT + BM) * FF];
__device__ __align__(16) float d_y[(size_t)NSLOT * H];
__device__ __align__(16) float d_xp[(size_t)NE * 16 * NI1 * 4096];  // packed A for gemm1
__device__ __align__(16) float d_ap[(size_t)NE * 16 * NI2 * 4096];  // packed A for gemm2
__device__ int   d_slot_token[NSLOT];
__device__ float d_slot_w[NSLOT];
__device__ int   d_token_slot[NSLOT];
__device__ int   d_topk_e[NSLOT];
__device__ float d_topk_w[NSLOT];
__device__ int   d_counts[NE];
__device__ int   d_offsets[NE];
__device__ int   d_cursor[NE];

// ===================== helpers =====================
__device__ __forceinline__ uint32_t f2tf(float f) {
    uint32_t r;
    asm("cvt.rna.tf32.f32 %0, %1;" : "=r"(r) : "f"(f));
    return r;
}
__device__ __forceinline__ void mma_tf32(float* c, uint32_t a0, uint32_t a1,
                                         uint32_t a2, uint32_t a3,
                                         uint32_t b0, uint32_t b1) {
    asm volatile(
        "mma.sync.aligned.m16n8k8.row.col.f32.tf32.tf32.f32 "
        "{%0,%1,%2,%3}, {%4,%5,%6,%7}, {%8,%9}, {%0,%1,%2,%3};\n"
        : "+f"(c[0]), "+f"(c[1]), "+f"(c[2]), "+f"(c[3])
        : "r"(a0), "r"(a1), "r"(a2), "r"(a3), "r"(b0), "r"(b1));
}
__device__ __forceinline__ uint32_t s2u(const void* p) {
    uint32_t a;
    asm("{ .reg .u64 t; cvta.to.shared.u64 t, %1; cvt.u32.u64 %0, t; }"
        : "=r"(a) : "l"(p));
    return a;
}
__device__ __forceinline__ void cpa16(uint32_t saddr, const void* gptr) {
    asm volatile("cp.async.cg.shared.global [%0], [%1], 16;" :: "r"(saddr), "l"(gptr));
}
__device__ __forceinline__ void cpa_commit() {
    asm volatile("cp.async.commit_group;" ::: "memory");
}
__device__ __forceinline__ void cpa_wait0() {
    asm volatile("cp.async.wait_group 0;" ::: "memory");
}
__device__ __forceinline__ uint4 lds128(const char* p) { return *(const uint4*)p; }

// ===================== small kernels =====================
__global__ void zero_counts_kernel() {
    if (threadIdx.x < NE) d_counts[threadIdx.x] = 0;
}

__global__ void router_kernel(const float* __restrict__ x,
                              const float* __restrict__ gw,
                              float* __restrict__ logits, int write_logits)
{
    int warp = (blockIdx.x * blockDim.x + threadIdx.x) >> 5;
    int lane = threadIdx.x & 31;
    if (warp >= T) return;
    const float* xr = x + (size_t)warp * H;

    float acc[NE];
#pragma unroll
    for (int e = 0; e < NE; e++) acc[e] = 0.f;
    for (int i = lane; i < H; i += 32) {
        float xv = xr[i];
#pragma unroll
        for (int e = 0; e < NE; e++) acc[e] += xv * gw[e * H + i];
    }
#pragma unroll
    for (int e = 0; e < NE; e++) {
#pragma unroll
        for (int off = 16; off > 0; off >>= 1)
            acc[e] += __shfl_xor_sync(0xffffffffu, acc[e], off);
    }
    if (lane == 0) {
        if (write_logits) {
#pragma unroll
            for (int e = 0; e < NE; e++) logits[warp * NE + e] = acc[e];
        }
        int i0 = 0;
#pragma unroll
        for (int e = 1; e < NE; e++) if (acc[e] > acc[i0]) i0 = e;
        int i1 = (i0 == 0) ? 1 : 0;
#pragma unroll
        for (int e = 0; e < NE; e++)
            if (e != i0 && acc[e] > acc[i1]) i1 = e;
        float m  = fmaxf(acc[i0], acc[i1]);
        float p0 = expf(acc[i0] - m), p1 = expf(acc[i1] - m);
        float inv = 1.f / (p0 + p1);
        d_topk_e[warp * 2 + 0] = i0;  d_topk_w[warp * 2 + 0] = p0 * inv;
        d_topk_e[warp * 2 + 1] = i1;  d_topk_w[warp * 2 + 1] = p1 * inv;
        atomicAdd(&d_counts[i0], 1);
        atomicAdd(&d_counts[i1], 1);
    }
}

__global__ void scan_kernel() {
    int off = 0;
    for (int e = 0; e < NE; e++) {
        d_offsets[e] = off;
        off += d_counts[e];
        d_cursor[e] = 0;
    }
}

__global__ void scatter_kernel() {
    int t = blockIdx.x * blockDim.x + threadIdx.x;
    if (t >= T) return;
#pragma unroll
    for (int k = 0; k < TK; k++) {
        int e   = d_topk_e[t * 2 + k];
        int pos = d_offsets[e] + atomicAdd(&d_cursor[e], 1);
        d_slot_token[pos]       = t;
        d_slot_w[pos]           = d_topk_w[t * 2 + k];
        d_token_slot[t * 2 + k] = pos;
    }
}

// ===================== A-tile packers =====================
// A blob (16KB) layout per (expert, mtile, ktile):
// 32 groups (tm 0..7, tk 0..3), group = tm*4+tk; lane l holds uint4 at
// group*512 + l*16:  {(mlo,klo),(mlo,khi),(mhi,klo),(mhi,khi)}
// mlo = tm*16 + (l>>2), mhi = mlo+8, klo = kt*32 + tk*8 + (l&3), khi = klo+4.
__global__ __launch_bounds__(256) void pack_x_kernel(const float* __restrict__ x)
{
    int e  = blockIdx.z, mt = blockIdx.y, kt = blockIdx.x;
    int cnt = d_counts[e];
    int m0  = mt * BM;
    if (m0 >= cnt) return;
    int seg = d_offsets[e];

    __shared__ int stok[BM];
    int t = threadIdx.x;
    if (t < BM) {
        int m = m0 + t;
        stok[t] = d_slot_token[seg + (m < cnt ? m : cnt - 1)];
    }
    __syncthreads();

    uint4* dst = (uint4*)(d_xp + ((size_t)(e * 16 + mt) * NI1 + kt) * 4096);
#pragma unroll
    for (int i = 0; i < 4; i++) {
        int idx = i * 256 + t;           // uint4 index 0..1023
        int grp = idx >> 5, l = idx & 31;
        int tm = grp >> 2, tk = grp & 3;
        int row = tm * 16 + (l >> 2);
        int k   = kt * 32 + tk * 8 + (l & 3);
        const float* r0 = x + (size_t)stok[row] * H + k;
        const float* r1 = x + (size_t)stok[row + 8] * H + k;
        uint4 v;
        v.x = f2tf(r0[0]);  v.y = f2tf(r0[4]);
        v.z = f2tf(r1[0]);  v.w = f2tf(r1[4]);
        dst[idx] = v;
    }
}

__global__ __launch_bounds__(256) void repack_act_kernel()
{
    int e  = blockIdx.z, mt = blockIdx.y, kt = blockIdx.x;
    int cnt = d_counts[e];
    int m0  = mt * BM;
    if (m0 >= cnt) return;
    int seg = d_offsets[e];

    int t = threadIdx.x;
    uint4* dst = (uint4*)(d_ap + ((size_t)(e * 16 + mt) * NI2 + kt) * 4096);
#pragma unroll
    for (int i = 0; i < 4; i++) {
        int idx = i * 256 + t;
        int grp = idx >> 5, l = idx & 31;
        int tm = grp >> 2, tk = grp & 3;
        int row = seg + m0 + tm * 16 + (l >> 2);
        int k   = kt * 32 + tk * 8 + (l & 3);
        const float* r0 = d_act + (size_t)row * FF + k;
        const float* r1 = d_act + (size_t)(row + 8) * FF + k;
        uint4 v;
        v.x = f2tf(r0[0]);  v.y = f2tf(r0[4]);
        v.z = f2tf(r1[0]);  v.w = f2tf(r1[4]);
        dst[idx] = v;
    }
}

// ===================== GEMM: cp.async A + reg-staged B, fragment-major =====================
// Stage (32KB): [A blob 16KB][B blob 16KB]. 2 stages.
// B blob: groups of 512B; gemm1: group = which*16 + tn*2 + tkp (which=gate/up, tn 0..7)
//         gemm2: group = tn*2 + tkp (tn 0..15)
// lane l of group: n = tn*8 + (l>>2); uint4 regs i: k = tkp*16 + (l&3) + 4i.
// A source selected INSIDE the kernel (device globals must not be passed from host).
template <int KTOT, bool IS1>
__global__ __launch_bounds__(256)
void moe_gemm_mma(const float* __restrict__ Wg)
{
    constexpr int NB = IS1 ? (2 * FF) : H;
    constexpr int NI = KTOT / BK;
    constexpr int STAGE = 32768;

    int e   = blockIdx.z;
    int cnt = d_counts[e];
    int m0  = blockIdx.x * BM;
    if (m0 >= cnt) return;
    int seg = d_offsets[e];

    extern __shared__ __align__(16) char smem[];
    uint32_t smem_u = s2u(smem);

    int t = threadIdx.x, w = t >> 5, lane = t & 31;
    int g = lane >> 2, tig = lane & 3;

    // ---------- B producer: warp w owns groups 4w..4w+3 ----------
    const float* pB[4];
    uint32_t stB[4];
#pragma unroll
    for (int j = 0; j < 4; j++) {
        int group = w * 4 + j;
        int tn, tkp, nglob;
        if (IS1) {
            int which = group >> 4, gi = group & 15;
            tn = gi >> 1;  tkp = gi & 1;
            nglob = which * FF + blockIdx.y * 64 + tn * 8 + g;
        } else {
            tn = group >> 1;  tkp = group & 1;
            nglob = blockIdx.y * 128 + tn * 8 + g;
        }
        pB[j] = Wg + (size_t)e * KTOT * NB + (size_t)(tkp * 16 + tig) * NB + nglob;
        stB[j] = 16384u + (uint32_t)group * 512u + (uint32_t)lane * 16u;
    }

    // ---------- A producer: cp.async of packed blob (device-global source) ----------
    const float* aBase = (IS1 ? d_xp : d_ap) + ((size_t)(e * 16 + blockIdx.x) * NI) * 4096;

    // ---------- consumer setup ----------
    constexpr int MT    = IS1 ? 2 : 4;
    constexpr int NSETS = IS1 ? 2 : 1;
    int mw = IS1 ? (w >> 1) : (w >> 2);
    int nw = IS1 ? (w & 1)  : (w & 3);

    uint32_t abase[MT];
#pragma unroll
    for (int mt = 0; mt < MT; mt++)
        abase[mt] = (uint32_t)(((mw * MT + mt) * 4) * 512 + lane * 16);
    uint32_t bbase[NSETS][4];
#pragma unroll
    for (int s = 0; s < NSETS; s++)
#pragma unroll
        for (int nt = 0; nt < 4; nt++) {
            int tn = nw * 4 + nt;
            bbase[s][nt] = (uint32_t)(16384 + (s * 16 + tn * 2) * 512 + lane * 16);
        }

    float acc[NSETS][MT][4][4];
#pragma unroll
    for (int s = 0; s < NSETS; s++)
#pragma unroll
        for (int mt = 0; mt < MT; mt++)
#pragma unroll
            for (int nt = 0; nt < 4; nt++)
#pragma unroll
                for (int q = 0; q < 4; q++) acc[s][mt][nt][q] = 0.f;

    // ---------- prologue ----------
#pragma unroll
    for (int i = 0; i < 4; i++)
        cpa16(smem_u + t * 16 + i * 4096, aBase + t * 4 + i * 1024);
    cpa_commit();

    float bv[4][4];
#pragma unroll
    for (int j = 0; j < 4; j++)
#pragma unroll
        for (int i = 0; i < 4; i++)
            bv[j][i] = __ldg(pB[j] + (size_t)(4 * i) * NB);

    // ---------- mainloop ----------
    for (int it = 0; it < NI; it++) {
        uint32_t sb = (it & 1) ? (uint32_t)STAGE : 0u;
        cpa_wait0();
        // store staged B regs (convert to tf32)
#pragma unroll
        for (int j = 0; j < 4; j++) {
            *(uint4*)(smem + sb + stB[j]) =
                make_uint4(f2tf(bv[j][0]), f2tf(bv[j][1]), f2tf(bv[j][2]), f2tf(bv[j][3]));
        }
        __syncthreads();
        if (it + 1 < NI) {
            uint32_t nb = sb ^ (uint32_t)STAGE;
            const float* aNext = aBase + (size_t)(it + 1) * 4096;
#pragma unroll
            for (int i = 0; i < 4; i++)
                cpa16(smem_u + nb + t * 16 + i * 4096, aNext + t * 4 + i * 1024);
            cpa_commit();
            int k0 = (it + 1) * BK;
#pragma unroll
            for (int j = 0; j < 4; j++)
#pragma unroll
                for (int i = 0; i < 4; i++)
                    bv[j][i] = __ldg(pB[j] + (size_t)(k0 + 4 * i) * NB);
        } else {
            cpa_commit();   // keep wait_group pairing trivial
        }
        // compute from this buffer
        const char* sm = smem + sb;
        uint4 bfr[NSETS][4];
#pragma unroll
        for (int ks = 0; ks < 4; ks++) {
            if ((ks & 1) == 0) {
                uint32_t tkpoff = (uint32_t)((ks >> 1) * 512);
#pragma unroll
                for (int s = 0; s < NSETS; s++)
#pragma unroll
                    for (int nt = 0; nt < 4; nt++)
                        bfr[s][nt] = lds128(sm + bbase[s][nt] + tkpoff);
            }
#pragma unroll
            for (int mt = 0; mt < MT; mt++) {
                uint4 af = lds128(sm + abase[mt] + (uint32_t)(ks * 512));
#pragma unroll
                for (int s = 0; s < NSETS; s++)
#pragma unroll
                    for (int nt = 0; nt < 4; nt++) {
                        uint32_t b0 = (ks & 1) ? bfr[s][nt].z : bfr[s][nt].x;
                        uint32_t b1 = (ks & 1) ? bfr[s][nt].w : bfr[s][nt].y;
                        mma_tf32(acc[s][mt][nt], af.x, af.z, af.y, af.w, b0, b1);
                    }
            }
        }
    }

    // ---------- epilogue ----------
    if (IS1) {
        int n0 = blockIdx.y * 64 + nw * 32;
#pragma unroll
        for (int mt = 0; mt < MT; mt++) {
#pragma unroll
            for (int rs = 0; rs < 2; rs++) {
                int m = m0 + mw * 32 + mt * 16 + g + rs * 8;
                if (m < cnt) {
                    int slot = seg + m;
                    float wgt = d_slot_w[slot];
                    float* row = d_act + (size_t)slot * FF + n0;
#pragma unroll
                    for (int nt = 0; nt < 4; nt++) {
                        float gv0 = acc[0][mt][nt][rs * 2 + 0];
                        float gv1 = acc[0][mt][nt][rs * 2 + 1];
                        float uv0 = acc[1][mt][nt][rs * 2 + 0];
                        float uv1 = acc[1][mt][nt][rs * 2 + 1];
                        float2 o;
                        o.x = gv0 / (1.f + expf(-gv0)) * uv0 * wgt;
                        o.y = gv1 / (1.f + expf(-gv1)) * uv1 * wgt;
                        *(float2*)(row + nt * 8 + 2 * tig) = o;
                    }
                }
            }
        }
    } else {
        int n0 = blockIdx.y * 128 + nw * 32;
#pragma unroll
        for (int mt = 0; mt < MT; mt++) {
#pragma unroll
            for (int rs = 0; rs < 2; rs++) {
                int m = m0 + mw * 64 + mt * 16 + g + rs * 8;
                if (m < cnt) {
                    int slot = seg + m;
                    float* row = d_y + (size_t)slot * H + n0;
#pragma unroll
                    for (int nt = 0; nt < 4; nt++) {
                        float2 o;
                        o.x = acc[0][mt][nt][rs * 2 + 0];
                        o.y = acc[0][mt][nt][rs * 2 + 1];
                        *(float2*)(row + nt * 8 + 2 * tig) = o;
                    }
                }
            }
        }
    }
}

// out[t, n] = y[slot0(t), n] + y[slot1(t), n]
__global__ void combine_kernel(float* __restrict__ out)
{
    int idx = blockIdx.x * blockDim.x + threadIdx.x;
    if (idx >= T * H) return;
    int t = idx >> 10;
    int n = idx & (H - 1);
    int s0 = d_token_slot[t * 2 + 0];
    int s1 = d_token_slot[t * 2 + 1];
    out[idx] = d_y[(size_t)s0 * H + n] + d_y[(size_t)s1 * H + n];
}

// ===================== launch =====================
extern "C" void kernel_launch(void* const* d_in, const int* in_sizes, int n_in,
                              void* d_out, int out_size)
{
    const float* x   = (const float*)d_in[0];   // [2,1024,1024]
    const float* gw  = (const float*)d_in[1];   // [8,1024]
    const float* wgu = (const float*)d_in[2];   // [8,1024,7168]
    const float* wdn = (const float*)d_in[3];   // [8,3584,1024]
    float* out = (float*)d_out;

    int write_logits = (out_size >= T * H + T * NE) ? 1 : 0;
    float* logits = out + (size_t)T * H;

    cudaFuncSetAttribute(moe_gemm_mma<H, true>,
                         cudaFuncAttributeMaxDynamicSharedMemorySize, SMEMSZ);
    cudaFuncSetAttribute(moe_gemm_mma<FF, false>,
                         cudaFuncAttributeMaxDynamicSharedMemorySize, SMEMSZ);

    zero_counts_kernel<<<1, 32>>>();
    router_kernel<<<(T * 32 + 255) / 256, 256>>>(x, gw, logits, write_logits);
    scan_kernel<<<1, 1>>>();
    scatter_kernel<<<(T + 255) / 256, 256>>>();
    pack_x_kernel<<<dim3(NI1, 16, NE), 256>>>(x);
    moe_gemm_mma<H, true><<<dim3(16, FF / 64, NE), 256, SMEMSZ>>>(wgu);   // (16, 56, 8)
    repack_act_kernel<<<dim3(NI2, 16, NE), 256>>>();
    moe_gemm_mma<FF, false><<<dim3(16, H / 128, NE), 256, SMEMSZ>>>(wdn); // (16, 8, 8)
    combine_kernel<<<(T * H + 255) / 256, 256>>>(out);
}

// round 7
// speedup vs baseline: 1.8174x; 1.3085x over previous
#include <cuda_runtime.h>
#include <math.h>
#include <stdint.h>

#define T   2048
#define H   1024
#define FF  3584
#define NE  8
#define TK  2
#define NSLOT (T*TK)

#define BM   128
#define BK   32
#define NI1  (H / BK)    // 32
#define NI2  (FF / BK)   // 112
#define NT1  (2*FF/128)  // 56 n-tiles (gemm1, 64 gate + 64 up each)
#define NT2  (H/128)     // 8 n-tiles (gemm2)
#define SMEMSZ 98304     // 3 stages x 32KB

// ---- scratch (device globals; no runtime allocation allowed) ----
__device__ __align__(16) float d_act[(size_t)(NSLOT + BM) * FF];
__device__ __align__(16) float d_y[(size_t)NSLOT * H];
__device__ __align__(16) float d_xp[(size_t)NE * 16 * NI1 * 4096];   // packed A gemm1
__device__ __align__(16) float d_ap[(size_t)NE * 16 * NI2 * 4096];   // packed A gemm2
__device__ __align__(16) float d_wp1[(size_t)NE * NT1 * NI1 * 4096]; // packed W gemm1 (235MB)
__device__ __align__(16) float d_wp2[(size_t)NE * NT2 * NI2 * 4096]; // packed W gemm2 (117MB)
__device__ int   d_slot_token[NSLOT];
__device__ float d_slot_w[NSLOT];
__device__ int   d_token_slot[NSLOT];
__device__ int   d_topk_e[NSLOT];
__device__ float d_topk_w[NSLOT];
__device__ int   d_counts[NE];
__device__ int   d_offsets[NE];
__device__ int   d_cursor[NE];

// ===================== helpers =====================
__device__ __forceinline__ uint32_t f2tf(float f) {
    uint32_t r;
    asm("cvt.rna.tf32.f32 %0, %1;" : "=r"(r) : "f"(f));
    return r;
}
__device__ __forceinline__ void mma_tf32(float* c, uint32_t a0, uint32_t a1,
                                         uint32_t a2, uint32_t a3,
                                         uint32_t b0, uint32_t b1) {
    asm volatile(
        "mma.sync.aligned.m16n8k8.row.col.f32.tf32.tf32.f32 "
        "{%0,%1,%2,%3}, {%4,%5,%6,%7}, {%8,%9}, {%0,%1,%2,%3};\n"
        : "+f"(c[0]), "+f"(c[1]), "+f"(c[2]), "+f"(c[3])
        : "r"(a0), "r"(a1), "r"(a2), "r"(a3), "r"(b0), "r"(b1));
}
__device__ __forceinline__ uint32_t s2u(const void* p) {
    uint32_t a;
    asm("{ .reg .u64 t; cvta.to.shared.u64 t, %1; cvt.u32.u64 %0, t; }"
        : "=r"(a) : "l"(p));
    return a;
}
__device__ __forceinline__ void cpa16(uint32_t saddr, const void* gptr) {
    asm volatile("cp.async.cg.shared.global [%0], [%1], 16;" :: "r"(saddr), "l"(gptr));
}
__device__ __forceinline__ void cpa_commit() {
    asm volatile("cp.async.commit_group;" ::: "memory");
}
__device__ __forceinline__ void cpa_wait1() {
    asm volatile("cp.async.wait_group 1;" ::: "memory");
}
__device__ __forceinline__ uint4 lds128(const char* p) { return *(const uint4*)p; }

// ===================== small kernels =====================
__global__ void zero_counts_kernel() {
    if (threadIdx.x < NE) d_counts[threadIdx.x] = 0;
}

__global__ void router_kernel(const float* __restrict__ x,
                              const float* __restrict__ gw,
                              float* __restrict__ logits, int write_logits)
{
    int warp = (blockIdx.x * blockDim.x + threadIdx.x) >> 5;
    int lane = threadIdx.x & 31;
    if (warp >= T) return;
    const float* xr = x + (size_t)warp * H;

    float acc[NE];
#pragma unroll
    for (int e = 0; e < NE; e++) acc[e] = 0.f;
    for (int i = lane; i < H; i += 32) {
        float xv = xr[i];
#pragma unroll
        for (int e = 0; e < NE; e++) acc[e] += xv * gw[e * H + i];
    }
#pragma unroll
    for (int e = 0; e < NE; e++) {
#pragma unroll
        for (int off = 16; off > 0; off >>= 1)
            acc[e] += __shfl_xor_sync(0xffffffffu, acc[e], off);
    }
    if (lane == 0) {
        if (write_logits) {
#pragma unroll
            for (int e = 0; e < NE; e++) logits[warp * NE + e] = acc[e];
        }
        int i0 = 0;
#pragma unroll
        for (int e = 1; e < NE; e++) if (acc[e] > acc[i0]) i0 = e;
        int i1 = (i0 == 0) ? 1 : 0;
#pragma unroll
        for (int e = 0; e < NE; e++)
            if (e != i0 && acc[e] > acc[i1]) i1 = e;
        float m  = fmaxf(acc[i0], acc[i1]);
        float p0 = expf(acc[i0] - m), p1 = expf(acc[i1] - m);
        float inv = 1.f / (p0 + p1);
        d_topk_e[warp * 2 + 0] = i0;  d_topk_w[warp * 2 + 0] = p0 * inv;
        d_topk_e[warp * 2 + 1] = i1;  d_topk_w[warp * 2 + 1] = p1 * inv;
        atomicAdd(&d_counts[i0], 1);
        atomicAdd(&d_counts[i1], 1);
    }
}

__global__ void scan_kernel() {
    int off = 0;
    for (int e = 0; e < NE; e++) {
        d_offsets[e] = off;
        off += d_counts[e];
        d_cursor[e] = 0;
    }
}

__global__ void scatter_kernel() {
    int t = blockIdx.x * blockDim.x + threadIdx.x;
    if (t >= T) return;
#pragma unroll
    for (int k = 0; k < TK; k++) {
        int e   = d_topk_e[t * 2 + k];
        int pos = d_offsets[e] + atomicAdd(&d_cursor[e], 1);
        d_slot_token[pos]       = t;
        d_slot_w[pos]           = d_topk_w[t * 2 + k];
        d_token_slot[t * 2 + k] = pos;
    }
}

// ===================== A-tile packers =====================
// A blob (16KB) per (expert, mtile, ktile): 32 groups (tm*4+tk), lane l uint4 at
// group*512 + l*16: {(mlo,klo),(mlo,khi),(mhi,klo),(mhi,khi)}
// mlo = tm*16+(l>>2), mhi = mlo+8, klo = kt*32+tk*8+(l&3), khi = klo+4.
__global__ __launch_bounds__(256) void pack_x_kernel(const float* __restrict__ x)
{
    int e  = blockIdx.z, mt = blockIdx.y, kt = blockIdx.x;
    int cnt = d_counts[e];
    int m0  = mt * BM;
    if (m0 >= cnt) return;
    int seg = d_offsets[e];

    __shared__ int stok[BM];
    int t = threadIdx.x;
    if (t < BM) {
        int m = m0 + t;
        stok[t] = d_slot_token[seg + (m < cnt ? m : cnt - 1)];
    }
    __syncthreads();

    uint4* dst = (uint4*)(d_xp + ((size_t)(e * 16 + mt) * NI1 + kt) * 4096);
#pragma unroll
    for (int i = 0; i < 4; i++) {
        int idx = i * 256 + t;
        int grp = idx >> 5, l = idx & 31;
        int tm = grp >> 2, tk = grp & 3;
        int row = tm * 16 + (l >> 2);
        int k   = kt * 32 + tk * 8 + (l & 3);
        const float* r0 = x + (size_t)stok[row] * H + k;
        const float* r1 = x + (size_t)stok[row + 8] * H + k;
        uint4 v;
        v.x = f2tf(r0[0]);  v.y = f2tf(r0[4]);
        v.z = f2tf(r1[0]);  v.w = f2tf(r1[4]);
        dst[idx] = v;
    }
}

__global__ __launch_bounds__(256) void repack_act_kernel()
{
    int e  = blockIdx.z, mt = blockIdx.y, kt = blockIdx.x;
    int cnt = d_counts[e];
    int m0  = mt * BM;
    if (m0 >= cnt) return;
    int seg = d_offsets[e];

    int t = threadIdx.x;
    uint4* dst = (uint4*)(d_ap + ((size_t)(e * 16 + mt) * NI2 + kt) * 4096);
#pragma unroll
    for (int i = 0; i < 4; i++) {
        int idx = i * 256 + t;
        int grp = idx >> 5, l = idx & 31;
        int tm = grp >> 2, tk = grp & 3;
        int row = seg + m0 + tm * 16 + (l >> 2);
        int k   = kt * 32 + tk * 8 + (l & 3);
        const float* r0 = d_act + (size_t)row * FF + k;
        const float* r1 = d_act + (size_t)(row + 8) * FF + k;
        uint4 v;
        v.x = f2tf(r0[0]);  v.y = f2tf(r0[4]);
        v.z = f2tf(r1[0]);  v.w = f2tf(r1[4]);
        dst[idx] = v;
    }
}

// ===================== W packers =====================
// B blob (16KB) per (expert, ntile, ktile): 32 groups of 512B.
// gemm1: group = which*16 + tn*2 + tkp; n = which*FF + nt*64 + tn*8 + (l>>2)
// gemm2: group = tn*2 + tkp;            n = nt*128 + tn*8 + (l>>2)
// lane l uint4 reg i: k = kt*32 + tkp*16 + (l&3) + 4i  (tf32-rounded)
template <bool IS1>
__global__ __launch_bounds__(256) void pack_w_kernel(const float* __restrict__ W)
{
    constexpr int KTOT = IS1 ? H : FF;
    constexpr int NB   = IS1 ? (2 * FF) : H;
    constexpr int NI   = IS1 ? NI1 : NI2;
    constexpr int NT   = IS1 ? NT1 : NT2;

    int e = blockIdx.z, nt = blockIdx.y, kt = blockIdx.x;
    int t = threadIdx.x;

    uint4* dst = (uint4*)((IS1 ? d_wp1 : d_wp2) +
                          ((size_t)(e * NT + nt) * NI + kt) * 4096);
    const float* Wb = W + (size_t)e * KTOT * NB;

#pragma unroll
    for (int i = 0; i < 4; i++) {
        int idx = i * 256 + t;
        int g2 = idx >> 5, l = idx & 31;
        int tn, tkp, n;
        if (IS1) {
            int which = g2 >> 4, gi = g2 & 15;
            tn = gi >> 1;  tkp = gi & 1;
            n = which * FF + nt * 64 + tn * 8 + (l >> 2);
        } else {
            tn = g2 >> 1;  tkp = g2 & 1;
            n = nt * 128 + tn * 8 + (l >> 2);
        }
        size_t k0 = (size_t)(kt * 32 + tkp * 16 + (l & 3));
        uint4 v;
        v.x = f2tf(Wb[(k0     ) * NB + n]);
        v.y = f2tf(Wb[(k0 +  4) * NB + n]);
        v.z = f2tf(Wb[(k0 +  8) * NB + n]);
        v.w = f2tf(Wb[(k0 + 12) * NB + n]);
        dst[idx] = v;
    }
}

// ===================== GEMM: all-cp.async, fragment-major, 3-stage =====================
// Stage (32KB): [A blob 16KB][B blob 16KB] x 3 stages. Everything pre-packed tf32.
template <int KTOT, bool IS1>
__global__ __launch_bounds__(256, 2)
void moe_gemm_mma()
{
    constexpr int NI = KTOT / BK;
    constexpr int NT = IS1 ? NT1 : NT2;
    constexpr uint32_t STG = 32768;

    int e   = blockIdx.z;
    int cnt = d_counts[e];
    int m0  = blockIdx.x * BM;
    if (m0 >= cnt) return;
    int seg = d_offsets[e];

    extern __shared__ __align__(16) char smem[];
    uint32_t smem_u = s2u(smem);

    int t = threadIdx.x, w = t >> 5, lane = t & 31;
    int g = lane >> 2, tig = lane & 3;

    const float* aBase = (IS1 ? d_xp : d_ap) + ((size_t)(e * 16 + blockIdx.x) * NI) * 4096;
    const float* bBase = (IS1 ? d_wp1 : d_wp2) + ((size_t)(e * NT + blockIdx.y) * NI) * 4096;

    // ---------- consumer setup ----------
    constexpr int MT    = IS1 ? 2 : 4;
    constexpr int NSETS = IS1 ? 2 : 1;
    int mw = IS1 ? (w >> 1) : (w >> 2);
    int nw = IS1 ? (w & 1)  : (w & 3);

    uint32_t abase[MT];
#pragma unroll
    for (int mt = 0; mt < MT; mt++)
        abase[mt] = (uint32_t)(((mw * MT + mt) * 4) * 512 + lane * 16);
    uint32_t bbase[NSETS][4];
#pragma unroll
    for (int s = 0; s < NSETS; s++)
#pragma unroll
        for (int nt = 0; nt < 4; nt++) {
            int tn = nw * 4 + nt;
            bbase[s][nt] = (uint32_t)(16384 + (s * 16 + tn * 2) * 512 + lane * 16);
        }

    float acc[NSETS][MT][4][4];
#pragma unroll
    for (int s = 0; s < NSETS; s++)
#pragma unroll
        for (int mt = 0; mt < MT; mt++)
#pragma unroll
            for (int nt = 0; nt < 4; nt++)
#pragma unroll
                for (int q = 0; q < 4; q++) acc[s][mt][nt][q] = 0.f;

    // ---------- prologue: fill stages 0 and 1 ----------
#pragma unroll
    for (int p = 0; p < 2; p++) {
        uint32_t sb = p * STG;
        const float* aSrc = aBase + (size_t)p * 4096;
        const float* bSrc = bBase + (size_t)p * 4096;
#pragma unroll
        for (int i = 0; i < 4; i++) {
            cpa16(smem_u + sb + t * 16 + i * 4096,          aSrc + t * 4 + i * 1024);
            cpa16(smem_u + sb + 16384 + t * 16 + i * 4096,  bSrc + t * 4 + i * 1024);
        }
        cpa_commit();
    }

    // ---------- mainloop ----------
    uint32_t sb = 0;  // stage byte offset of current buffer
    for (int it = 0; it < NI; it++) {
        cpa_wait1();          // current stage landed (next may be in flight)
        __syncthreads();
        if (it + 2 < NI) {
            uint32_t nb = sb + 2 * STG;
            if (nb >= 3 * STG) nb -= 3 * STG;
            const float* aSrc = aBase + (size_t)(it + 2) * 4096;
            const float* bSrc = bBase + (size_t)(it + 2) * 4096;
#pragma unroll
            for (int i = 0; i < 4; i++) {
                cpa16(smem_u + nb + t * 16 + i * 4096,          aSrc + t * 4 + i * 1024);
                cpa16(smem_u + nb + 16384 + t * 16 + i * 4096,  bSrc + t * 4 + i * 1024);
            }
            cpa_commit();
        }
        const char* sm = smem + sb;
        uint4 bfr[NSETS][4];
#pragma unroll
        for (int ks = 0; ks < 4; ks++) {
            if ((ks & 1) == 0) {
                uint32_t tkpoff = (uint32_t)((ks >> 1) * 512);
#pragma unroll
                for (int s = 0; s < NSETS; s++)
#pragma unroll
                    for (int nt = 0; nt < 4; nt++)
                        bfr[s][nt] = lds128(sm + bbase[s][nt] + tkpoff);
            }
#pragma unroll
            for (int mt = 0; mt < MT; mt++) {
                uint4 af = lds128(sm + abase[mt] + (uint32_t)(ks * 512));
#pragma unroll
                for (int s = 0; s < NSETS; s++)
#pragma unroll
                    for (int nt = 0; nt < 4; nt++) {
                        uint32_t b0 = (ks & 1) ? bfr[s][nt].z : bfr[s][nt].x;
                        uint32_t b1 = (ks & 1) ? bfr[s][nt].w : bfr[s][nt].y;
                        mma_tf32(acc[s][mt][nt], af.x, af.z, af.y, af.w, b0, b1);
                    }
            }
        }
        sb += STG;
        if (sb >= 3 * STG) sb = 0;
    }

    // ---------- epilogue ----------
    if (IS1) {
        int n0 = blockIdx.y * 64 + nw * 32;
#pragma unroll
        for (int mt = 0; mt < MT; mt++) {
#pragma unroll
            for (int rs = 0; rs < 2; rs++) {
                int m = m0 + mw * 32 + mt * 16 + g + rs * 8;
                if (m < cnt) {
                    int slot = seg + m;
                    float wgt = d_slot_w[slot];
                    float* row = d_act + (size_t)slot * FF + n0;
#pragma unroll
                    for (int nt = 0; nt < 4; nt++) {
                        float gv0 = acc[0][mt][nt][rs * 2 + 0];
                        float gv1 = acc[0][mt][nt][rs * 2 + 1];
                        float uv0 = acc[1][mt][nt][rs * 2 + 0];
                        float uv1 = acc[1][mt][nt][rs * 2 + 1];
                        float2 o;
                        o.x = gv0 / (1.f + expf(-gv0)) * uv0 * wgt;
                        o.y = gv1 / (1.f + expf(-gv1)) * uv1 * wgt;
                        *(float2*)(row + nt * 8 + 2 * tig) = o;
                    }
                }
            }
        }
    } else {
        int n0 = blockIdx.y * 128 + nw * 32;
#pragma unroll
        for (int mt = 0; mt < MT; mt++) {
#pragma unroll
            for (int rs = 0; rs < 2; rs++) {
                int m = m0 + mw * 64 + mt * 16 + g + rs * 8;
                if (m < cnt) {
                    int slot = seg + m;
                    float* row = d_y + (size_t)slot * H + n0;
#pragma unroll
                    for (int nt = 0; nt < 4; nt++) {
                        float2 o;
                        o.x = acc[0][mt][nt][rs * 2 + 0];
                        o.y = acc[0][mt][nt][rs * 2 + 1];
                        *(float2*)(row + nt * 8 + 2 * tig) = o;
                    }
                }
            }
        }
    }
}

// out[t, n] = y[slot0(t), n] + y[slot1(t), n]
__global__ void combine_kernel(float* __restrict__ out)
{
    int idx = blockIdx.x * blockDim.x + threadIdx.x;
    if (idx >= T * H) return;
    int t = idx >> 10;
    int n = idx & (H - 1);
    int s0 = d_token_slot[t * 2 + 0];
    int s1 = d_token_slot[t * 2 + 1];
    out[idx] = d_y[(size_t)s0 * H + n] + d_y[(size_t)s1 * H + n];
}

// ===================== launch =====================
extern "C" void kernel_launch(void* const* d_in, const int* in_sizes, int n_in,
                              void* d_out, int out_size)
{
    const float* x   = (const float*)d_in[0];   // [2,1024,1024]
    const float* gw  = (const float*)d_in[1];   // [8,1024]
    const float* wgu = (const float*)d_in[2];   // [8,1024,7168]
    const float* wdn = (const float*)d_in[3];   // [8,3584,1024]
    float* out = (float*)d_out;

    int write_logits = (out_size >= T * H + T * NE) ? 1 : 0;
    float* logits = out + (size_t)T * H;

    cudaFuncSetAttribute(moe_gemm_mma<H, true>,
                         cudaFuncAttributeMaxDynamicSharedMemorySize, SMEMSZ);
    cudaFuncSetAttribute(moe_gemm_mma<FF, false>,
                         cudaFuncAttributeMaxDynamicSharedMemorySize, SMEMSZ);

    zero_counts_kernel<<<1, 32>>>();
    router_kernel<<<(T * 32 + 255) / 256, 256>>>(x, gw, logits, write_logits);
    scan_kernel<<<1, 1>>>();
    scatter_kernel<<<(T + 255) / 256, 256>>>();
    pack_w_kernel<true><<<dim3(NI1, NT1, NE), 256>>>(wgu);
    pack_x_kernel<<<dim3(NI1, 16, NE), 256>>>(x);
    moe_gemm_mma<H, true><<<dim3(16, NT1, NE), 256, SMEMSZ>>>();    // (16, 56, 8)
    pack_w_kernel<false><<<dim3(NI2, NT2, NE), 256>>>(wdn);
    repack_act_kernel<<<dim3(NI2, 16, NE), 256>>>();
    moe_gemm_mma<FF, false><<<dim3(16, NT2, NE), 256, SMEMSZ>>>();  // (16, 8, 8)
    combine_kernel<<<(T * H + 255) / 256, 256>>>(out);
}

// round 8
// speedup vs baseline: 1.8596x; 1.0232x over previous
#include <cuda_runtime.h>
#include <math.h>
#include <stdint.h>

#define T   2048
#define H   1024
#define FF  3584
#define NE  8
#define TK  2
#define NSLOT (T*TK)

#define BM   128
#define BK   32
#define NI1  (H / BK)    // 32
#define NI2  (FF / BK)   // 112
#define NT1  (2*FF/128)  // 56 n-tiles (gemm1: 64 gate + 64 up each)
#define NT2  (H/128)     // 8 n-tiles (gemm2)
#define SMEMSZ 98304     // 3 stages x 32KB

// ---- scratch (device globals; no runtime allocation allowed) ----
__device__ __align__(16) float d_xp[(size_t)NE * 16 * NI1 * 4096];   // packed A gemm1
__device__ __align__(16) float d_ap[(size_t)NE * 16 * NI2 * 4096];   // packed A gemm2 (written by gemm1)
__device__ __align__(16) float d_wp1[(size_t)NE * NT1 * NI1 * 4096]; // packed W gemm1
__device__ __align__(16) float d_wp2[(size_t)NE * NT2 * NI2 * 4096]; // packed W gemm2
__device__ int   d_slot_token[NSLOT];
__device__ float d_slot_w[NSLOT];
__device__ int   d_topk_e[NSLOT];
__device__ float d_topk_w[NSLOT];
__device__ int   d_counts[NE];
__device__ int   d_offsets[NE];
__device__ int   d_cursor[NE];

// ===================== helpers =====================
__device__ __forceinline__ uint32_t f2tf(float f) {
    uint32_t r;
    asm("cvt.rna.tf32.f32 %0, %1;" : "=r"(r) : "f"(f));
    return r;
}
__device__ __forceinline__ void mma_tf32(float* c, uint32_t a0, uint32_t a1,
                                         uint32_t a2, uint32_t a3,
                                         uint32_t b0, uint32_t b1) {
    asm volatile(
        "mma.sync.aligned.m16n8k8.row.col.f32.tf32.tf32.f32 "
        "{%0,%1,%2,%3}, {%4,%5,%6,%7}, {%8,%9}, {%0,%1,%2,%3};\n"
        : "+f"(c[0]), "+f"(c[1]), "+f"(c[2]), "+f"(c[3])
        : "r"(a0), "r"(a1), "r"(a2), "r"(a3), "r"(b0), "r"(b1));
}
__device__ __forceinline__ uint32_t s2u(const void* p) {
    uint32_t a;
    asm("{ .reg .u64 t; cvta.to.shared.u64 t, %1; cvt.u32.u64 %0, t; }"
        : "=r"(a) : "l"(p));
    return a;
}
__device__ __forceinline__ void cpa16(uint32_t saddr, const void* gptr) {
    asm volatile("cp.async.cg.shared.global [%0], [%1], 16;" :: "r"(saddr), "l"(gptr));
}
__device__ __forceinline__ void cpa_commit() {
    asm volatile("cp.async.commit_group;" ::: "memory");
}
__device__ __forceinline__ void cpa_wait1() {
    asm volatile("cp.async.wait_group 1;" ::: "memory");
}
__device__ __forceinline__ void cpa_wait0() {
    asm volatile("cp.async.wait_group 0;" ::: "memory");
}
__device__ __forceinline__ uint4 lds128(const char* p) { return *(const uint4*)p; }
__device__ __forceinline__ float shf(float v, int src) {
    return __shfl_sync(0xffffffffu, v, src);
}
__device__ __forceinline__ float silu(float g) { return g / (1.f + expf(-g)); }

// ===================== small kernels =====================
__global__ void zero_out_kernel(float* __restrict__ out) {
    int idx = blockIdx.x * blockDim.x + threadIdx.x;
    if (idx < T * H) out[idx] = 0.f;
}

__global__ void router_kernel(const float* __restrict__ x,
                              const float* __restrict__ gw,
                              float* __restrict__ logits, int write_logits)
{
    int warp = (blockIdx.x * blockDim.x + threadIdx.x) >> 5;
    int lane = threadIdx.x & 31;
    if (warp >= T) return;
    const float* xr = x + (size_t)warp * H;

    float acc[NE];
#pragma unroll
    for (int e = 0; e < NE; e++) acc[e] = 0.f;
    for (int i = lane; i < H; i += 32) {
        float xv = xr[i];
#pragma unroll
        for (int e = 0; e < NE; e++) acc[e] += xv * gw[e * H + i];
    }
#pragma unroll
    for (int e = 0; e < NE; e++) {
#pragma unroll
        for (int off = 16; off > 0; off >>= 1)
            acc[e] += __shfl_xor_sync(0xffffffffu, acc[e], off);
    }
    if (lane == 0) {
        if (write_logits) {
#pragma unroll
            for (int e = 0; e < NE; e++) logits[warp * NE + e] = acc[e];
        }
        int i0 = 0;
#pragma unroll
        for (int e = 1; e < NE; e++) if (acc[e] > acc[i0]) i0 = e;
        int i1 = (i0 == 0) ? 1 : 0;
#pragma unroll
        for (int e = 0; e < NE; e++)
            if (e != i0 && acc[e] > acc[i1]) i1 = e;
        float m  = fmaxf(acc[i0], acc[i1]);
        float p0 = expf(acc[i0] - m), p1 = expf(acc[i1] - m);
        float inv = 1.f / (p0 + p1);
        d_topk_e[warp * 2 + 0] = i0;  d_topk_w[warp * 2 + 0] = p0 * inv;
        d_topk_e[warp * 2 + 1] = i1;  d_topk_w[warp * 2 + 1] = p1 * inv;
    }
}

// histogram + prefix + cursor reset, one block
__global__ void hist_scan_kernel() {
    __shared__ int h[NE];
    int t = threadIdx.x;
    if (t < NE) h[t] = 0;
    __syncthreads();
    for (int i = t; i < NSLOT; i += blockDim.x)
        atomicAdd(&h[d_topk_e[i]], 1);
    __syncthreads();
    if (t == 0) {
        int off = 0;
        for (int e = 0; e < NE; e++) {
            d_counts[e]  = h[e];
            d_offsets[e] = off;
            off += h[e];
            d_cursor[e] = 0;
        }
    }
}

__global__ void scatter_kernel() {
    int t = blockIdx.x * blockDim.x + threadIdx.x;
    if (t >= T) return;
#pragma unroll
    for (int k = 0; k < TK; k++) {
        int e   = d_topk_e[t * 2 + k];
        int pos = d_offsets[e] + atomicAdd(&d_cursor[e], 1);
        d_slot_token[pos] = t;
        d_slot_w[pos]     = d_topk_w[t * 2 + k];
    }
}

// ===================== A packer (gemm1 input) =====================
// Blob (16KB) per (expert, mtile, ktile): 32 groups (tm*4+tk), lane l uint4 at
// group*512 + l*16: {(mlo,klo),(mlo,khi),(mhi,klo),(mhi,khi)}
// mlo = tm*16+(l>>2), mhi = mlo+8, klo = kt*32+tk*8+(l&3), khi = klo+4.
__global__ __launch_bounds__(256) void pack_x_kernel(const float* __restrict__ x)
{
    int e  = blockIdx.z, mt = blockIdx.y, kt = blockIdx.x;
    int cnt = d_counts[e];
    int m0  = mt * BM;
    if (m0 >= cnt) return;
    int seg = d_offsets[e];

    __shared__ int stok[BM];
    int t = threadIdx.x;
    if (t < BM) {
        int m = m0 + t;
        stok[t] = d_slot_token[seg + (m < cnt ? m : cnt - 1)];
    }
    __syncthreads();

    uint4* dst = (uint4*)(d_xp + ((size_t)(e * 16 + mt) * NI1 + kt) * 4096);
#pragma unroll
    for (int i = 0; i < 4; i++) {
        int idx = i * 256 + t;
        int grp = idx >> 5, l = idx & 31;
        int tm = grp >> 2, tk = grp & 3;
        int row = tm * 16 + (l >> 2);
        int k   = kt * 32 + tk * 8 + (l & 3);
        const float* r0 = x + (size_t)stok[row] * H + k;
        const float* r1 = x + (size_t)stok[row + 8] * H + k;
        uint4 v;
        v.x = f2tf(r0[0]);  v.y = f2tf(r0[4]);
        v.z = f2tf(r1[0]);  v.w = f2tf(r1[4]);
        dst[idx] = v;
    }
}

// ===================== W packers =====================
template <bool IS1>
__global__ __launch_bounds__(256) void pack_w_kernel(const float* __restrict__ W)
{
    constexpr int KTOT = IS1 ? H : FF;
    constexpr int NB   = IS1 ? (2 * FF) : H;
    constexpr int NI   = IS1 ? NI1 : NI2;
    constexpr int NT   = IS1 ? NT1 : NT2;

    int e = blockIdx.z, nt = blockIdx.y, kt = blockIdx.x;
    int t = threadIdx.x;

    uint4* dst = (uint4*)((IS1 ? d_wp1 : d_wp2) +
                          ((size_t)(e * NT + nt) * NI + kt) * 4096);
    const float* Wb = W + (size_t)e * KTOT * NB;

#pragma unroll
    for (int i = 0; i < 4; i++) {
        int idx = i * 256 + t;
        int g2 = idx >> 5, l = idx & 31;
        int tn, tkp, n;
        if (IS1) {
            int which = g2 >> 4, gi = g2 & 15;
            tn = gi >> 1;  tkp = gi & 1;
            n = which * FF + nt * 64 + tn * 8 + (l >> 2);
        } else {
            tn = g2 >> 1;  tkp = g2 & 1;
            n = nt * 128 + tn * 8 + (l >> 2);
        }
        size_t k0 = (size_t)(kt * 32 + tkp * 16 + (l & 3));
        uint4 v;
        v.x = f2tf(Wb[(k0     ) * NB + n]);
        v.y = f2tf(Wb[(k0 +  4) * NB + n]);
        v.z = f2tf(Wb[(k0 +  8) * NB + n]);
        v.w = f2tf(Wb[(k0 + 12) * NB + n]);
        dst[idx] = v;
    }
}

// ===================== GEMM =====================
// IS1: epilogue writes d_ap (gemm2's packed A) directly via shfl permute.
// !IS1: epilogue atomically adds into out[token].
template <int KTOT, bool IS1>
__global__ __launch_bounds__(256, 2)
void moe_gemm_mma(float* __restrict__ out)
{
    constexpr int NI = KTOT / BK;
    constexpr int NT = IS1 ? NT1 : NT2;
    constexpr uint32_t STG = 32768;

    int e   = blockIdx.z;
    int cnt = d_counts[e];
    int m0  = blockIdx.x * BM;
    if (m0 >= cnt) return;
    int seg = d_offsets[e];

    extern __shared__ __align__(16) char smem[];
    uint32_t smem_u = s2u(smem);

    int t = threadIdx.x, w = t >> 5, lane = t & 31;
    int g = lane >> 2, tig = lane & 3;

    const float* aBase = (IS1 ? d_xp : d_ap) + ((size_t)(e * 16 + blockIdx.x) * NI) * 4096;
    const float* bBase = (IS1 ? d_wp1 : d_wp2) + ((size_t)(e * NT + blockIdx.y) * NI) * 4096;

    constexpr int MT    = IS1 ? 2 : 4;
    constexpr int NSETS = IS1 ? 2 : 1;
    int mw = IS1 ? (w >> 1) : (w >> 2);
    int nw = IS1 ? (w & 1)  : (w & 3);

    uint32_t abase[MT];
#pragma unroll
    for (int mt = 0; mt < MT; mt++)
        abase[mt] = (uint32_t)(((mw * MT + mt) * 4) * 512 + lane * 16);
    uint32_t bbase[NSETS][4];
#pragma unroll
    for (int s = 0; s < NSETS; s++)
#pragma unroll
        for (int nt = 0; nt < 4; nt++) {
            int tn = nw * 4 + nt;
            bbase[s][nt] = (uint32_t)(16384 + (s * 16 + tn * 2) * 512 + lane * 16);
        }

    float acc[NSETS][MT][4][4];
#pragma unroll
    for (int s = 0; s < NSETS; s++)
#pragma unroll
        for (int mt = 0; mt < MT; mt++)
#pragma unroll
            for (int nt = 0; nt < 4; nt++)
#pragma unroll
                for (int q = 0; q < 4; q++) acc[s][mt][nt][q] = 0.f;

    // ---------- prologue: fill stages 0 and 1 ----------
#pragma unroll
    for (int p = 0; p < 2; p++) {
        uint32_t sb = p * STG;
        const float* aSrc = aBase + (size_t)p * 4096;
        const float* bSrc = bBase + (size_t)p * 4096;
#pragma unroll
        for (int i = 0; i < 4; i++) {
            cpa16(smem_u + sb + t * 16 + i * 4096,          aSrc + t * 4 + i * 1024);
            cpa16(smem_u + sb + 16384 + t * 16 + i * 4096,  bSrc + t * 4 + i * 1024);
        }
        cpa_commit();
    }

    // ---------- mainloop ----------
    uint32_t sb = 0;
    for (int it = 0; it < NI; it++) {
        if (it == NI - 1) cpa_wait0(); else cpa_wait1();
        __syncthreads();
        if (it + 2 < NI) {
            uint32_t nb = sb + 2 * STG;
            if (nb >= 3 * STG) nb -= 3 * STG;
            const float* aSrc = aBase + (size_t)(it + 2) * 4096;
            const float* bSrc = bBase + (size_t)(it + 2) * 4096;
#pragma unroll
            for (int i = 0; i < 4; i++) {
                cpa16(smem_u + nb + t * 16 + i * 4096,          aSrc + t * 4 + i * 1024);
                cpa16(smem_u + nb + 16384 + t * 16 + i * 4096,  bSrc + t * 4 + i * 1024);
            }
            cpa_commit();
        }
        const char* sm = smem + sb;
        uint4 bfr[NSETS][4];
#pragma unroll
        for (int ks = 0; ks < 4; ks++) {
            if ((ks & 1) == 0) {
                uint32_t tkpoff = (uint32_t)((ks >> 1) * 512);
#pragma unroll
                for (int s = 0; s < NSETS; s++)
#pragma unroll
                    for (int nt = 0; nt < 4; nt++)
                        bfr[s][nt] = lds128(sm + bbase[s][nt] + tkpoff);
            }
#pragma unroll
            for (int mt = 0; mt < MT; mt++) {
                uint4 af = lds128(sm + abase[mt] + (uint32_t)(ks * 512));
#pragma unroll
                for (int s = 0; s < NSETS; s++)
#pragma unroll
                    for (int nt = 0; nt < 4; nt++) {
                        uint32_t b0 = (ks & 1) ? bfr[s][nt].z : bfr[s][nt].x;
                        uint32_t b1 = (ks & 1) ? bfr[s][nt].w : bfr[s][nt].y;
                        mma_tf32(acc[s][mt][nt], af.x, af.z, af.y, af.w, b0, b1);
                    }
            }
        }
        sb += STG;
        if (sb >= 3 * STG) sb = 0;
    }

    // ---------- epilogue ----------
    if (IS1) {
        // write gemm2's packed A blob directly: kt2 = by*2 + nw
        char* blob = (char*)(d_ap + ((size_t)(e * 16 + blockIdx.x) * NI2
                                     + (blockIdx.y * 2 + nw)) * 4096);
        int baseLane = lane & ~3;
        int c  = tig;
        int sl = baseLane + (c >> 1);
        int sh = sl + 2;
#pragma unroll
        for (int mt = 0; mt < MT; mt++) {
            int mlo = mw * 32 + mt * 16 + g;
            float wlo = d_slot_w[seg + min(m0 + mlo,     cnt - 1)];
            float whi = d_slot_w[seg + min(m0 + mlo + 8, cnt - 1)];
#pragma unroll
            for (int nt = 0; nt < 4; nt++) {
                float a0 = silu(acc[0][mt][nt][0]) * acc[1][mt][nt][0] * wlo;
                float a1 = silu(acc[0][mt][nt][1]) * acc[1][mt][nt][1] * wlo;
                float a2 = silu(acc[0][mt][nt][2]) * acc[1][mt][nt][2] * whi;
                float a3 = silu(acc[0][mt][nt][3]) * acc[1][mt][nt][3] * whi;
                float x00 = shf(a0, sl), x01 = shf(a1, sl);
                float x10 = shf(a0, sh), x11 = shf(a1, sh);
                float x20 = shf(a2, sl), x21 = shf(a3, sl);
                float x30 = shf(a2, sh), x31 = shf(a3, sh);
                float vll = (c & 1) ? x01 : x00;
                float vlh = (c & 1) ? x11 : x10;
                float vhl = (c & 1) ? x21 : x20;
                float vhh = (c & 1) ? x31 : x30;
                uint4 v = make_uint4(f2tf(vll), f2tf(vlh), f2tf(vhl), f2tf(vhh));
                *(uint4*)(blob + ((mw * 2 + mt) * 4 + nt) * 512 + lane * 16) = v;
            }
        }
    } else {
        int n0 = blockIdx.y * 128 + nw * 32;
#pragma unroll
        for (int mt = 0; mt < MT; mt++) {
#pragma unroll
            for (int rs = 0; rs < 2; rs++) {
                int m = m0 + mw * 64 + mt * 16 + g + rs * 8;
                if (m < cnt) {
                    int tok = d_slot_token[seg + m];
                    float* row = out + (size_t)tok * H + n0;
#pragma unroll
                    for (int nt = 0; nt < 4; nt++) {
                        atomicAdd(&row[nt * 8 + 2 * tig],     acc[0][mt][nt][rs * 2 + 0]);
                        atomicAdd(&row[nt * 8 + 2 * tig + 1], acc[0][mt][nt][rs * 2 + 1]);
                    }
                }
            }
        }
    }
}

// ===================== launch =====================
extern "C" void kernel_launch(void* const* d_in, const int* in_sizes, int n_in,
                              void* d_out, int out_size)
{
    const float* x   = (const float*)d_in[0];   // [2,1024,1024]
    const float* gw  = (const float*)d_in[1];   // [8,1024]
    const float* wgu = (const float*)d_in[2];   // [8,1024,7168]
    const float* wdn = (const float*)d_in[3];   // [8,3584,1024]
    float* out = (float*)d_out;

    int write_logits = (out_size >= T * H + T * NE) ? 1 : 0;
    float* logits = out + (size_t)T * H;

    cudaFuncSetAttribute(moe_gemm_mma<H, true>,
                         cudaFuncAttributeMaxDynamicSharedMemorySize, SMEMSZ);
    cudaFuncSetAttribute(moe_gemm_mma<FF, false>,
                         cudaFuncAttributeMaxDynamicSharedMemorySize, SMEMSZ);

    zero_out_kernel<<<(T * H + 255) / 256, 256>>>(out);
    router_kernel<<<(T * 32 + 255) / 256, 256>>>(x, gw, logits, write_logits);
    hist_scan_kernel<<<1, 256>>>();
    scatter_kernel<<<(T + 255) / 256, 256>>>();
    pack_w_kernel<true><<<dim3(NI1, NT1, NE), 256>>>(wgu);
    pack_x_kernel<<<dim3(NI1, 16, NE), 256>>>(x);
    moe_gemm_mma<H, true><<<dim3(16, NT1, NE), 256, SMEMSZ>>>(nullptr);  // (16, 56, 8)
    pack_w_kernel<false><<<dim3(NI2, NT2, NE), 256>>>(wdn);
    moe_gemm_mma<FF, false><<<dim3(16, NT2, NE), 256, SMEMSZ>>>(out);    // (16, 8, 8)
}

// round 9
// speedup vs baseline: 3.4218x; 1.8401x over previous
#include <cuda_runtime.h>
#include <cuda_fp16.h>
#include <math.h>
#include <stdint.h>

#define T   2048
#define H   1024
#define FF  3584
#define NE  8
#define TK  2
#define NSLOT (T*TK)

#define BM   128
#define BK   64
#define NI1  (H / BK)    // 16
#define NI2  (FF / BK)   // 56
#define NT1  (2*FF/128)  // 56 n-tiles (gemm1: 64 gate + 64 up cols each)
#define NT2  (H/128)     // 8 n-tiles (gemm2)
#define SMEMSZ 98304     // 3 stages x 32KB

// ---- scratch (device globals, fp16 fragment-major blobs of 16KB = 1024 uint4) ----
__device__ __align__(16) uint4 d_xp [(size_t)NE * 16 * NI1 * 1024];  // 33.5MB
__device__ __align__(16) uint4 d_ap [(size_t)NE * 16 * NI2 * 1024];  // 117MB (written by gemm1)
__device__ __align__(16) uint4 d_wp1[(size_t)NE * NT1 * NI1 * 1024]; // 117MB
__device__ __align__(16) uint4 d_wp2[(size_t)NE * NT2 * NI2 * 1024]; // 58.7MB
__device__ int   d_slot_token[NSLOT];
__device__ float d_slot_w[NSLOT];
__device__ int   d_topk_e[NSLOT];
__device__ float d_topk_w[NSLOT];
__device__ int   d_counts[NE];
__device__ int   d_offsets[NE];
__device__ int   d_cursor[NE];

// ===================== helpers =====================
__device__ __forceinline__ uint32_t pk2(float lo, float hi) {
    __half2 h = __floats2half2_rn(lo, hi);
    return *(uint32_t*)&h;
}
__device__ __forceinline__ void mma_fp16(float* c, uint32_t a0, uint32_t a1,
                                         uint32_t a2, uint32_t a3,
                                         uint32_t b0, uint32_t b1) {
    asm volatile(
        "mma.sync.aligned.m16n8k16.row.col.f32.f16.f16.f32 "
        "{%0,%1,%2,%3}, {%4,%5,%6,%7}, {%8,%9}, {%0,%1,%2,%3};\n"
        : "+f"(c[0]), "+f"(c[1]), "+f"(c[2]), "+f"(c[3])
        : "r"(a0), "r"(a1), "r"(a2), "r"(a3), "r"(b0), "r"(b1));
}
__device__ __forceinline__ uint32_t s2u(const void* p) {
    uint32_t a;
    asm("{ .reg .u64 t; cvta.to.shared.u64 t, %1; cvt.u32.u64 %0, t; }"
        : "=r"(a) : "l"(p));
    return a;
}
__device__ __forceinline__ void cpa16(uint32_t saddr, const void* gptr) {
    asm volatile("cp.async.cg.shared.global [%0], [%1], 16;" :: "r"(saddr), "l"(gptr));
}
__device__ __forceinline__ void cpa_commit() {
    asm volatile("cp.async.commit_group;" ::: "memory");
}
__device__ __forceinline__ void cpa_wait1() {
    asm volatile("cp.async.wait_group 1;" ::: "memory");
}
__device__ __forceinline__ void cpa_wait0() {
    asm volatile("cp.async.wait_group 0;" ::: "memory");
}
__device__ __forceinline__ uint4 lds128(const char* p) { return *(const uint4*)p; }
__device__ __forceinline__ float silu(float g) { return g / (1.f + expf(-g)); }

// ===================== small kernels =====================
__global__ void zero_out_kernel(float* __restrict__ out) {
    int idx = blockIdx.x * blockDim.x + threadIdx.x;
    if (idx < T * H) out[idx] = 0.f;
}

__global__ void router_kernel(const float* __restrict__ x,
                              const float* __restrict__ gw,
                              float* __restrict__ logits, int write_logits)
{
    int warp = (blockIdx.x * blockDim.x + threadIdx.x) >> 5;
    int lane = threadIdx.x & 31;
    if (warp >= T) return;
    const float* xr = x + (size_t)warp * H;

    float acc[NE];
#pragma unroll
    for (int e = 0; e < NE; e++) acc[e] = 0.f;
    for (int i = lane; i < H; i += 32) {
        float xv = xr[i];
#pragma unroll
        for (int e = 0; e < NE; e++) acc[e] += xv * gw[e * H + i];
    }
#pragma unroll
    for (int e = 0; e < NE; e++) {
#pragma unroll
        for (int off = 16; off > 0; off >>= 1)
            acc[e] += __shfl_xor_sync(0xffffffffu, acc[e], off);
    }
    if (lane == 0) {
        if (write_logits) {
#pragma unroll
            for (int e = 0; e < NE; e++) logits[warp * NE + e] = acc[e];
        }
        int i0 = 0;
#pragma unroll
        for (int e = 1; e < NE; e++) if (acc[e] > acc[i0]) i0 = e;
        int i1 = (i0 == 0) ? 1 : 0;
#pragma unroll
        for (int e = 0; e < NE; e++)
            if (e != i0 && acc[e] > acc[i1]) i1 = e;
        float m  = fmaxf(acc[i0], acc[i1]);
        float p0 = expf(acc[i0] - m), p1 = expf(acc[i1] - m);
        float inv = 1.f / (p0 + p1);
        d_topk_e[warp * 2 + 0] = i0;  d_topk_w[warp * 2 + 0] = p0 * inv;
        d_topk_e[warp * 2 + 1] = i1;  d_topk_w[warp * 2 + 1] = p1 * inv;
    }
}

__global__ void hist_scan_kernel() {
    __shared__ int h[NE];
    int t = threadIdx.x;
    if (t < NE) h[t] = 0;
    __syncthreads();
    for (int i = t; i < NSLOT; i += blockDim.x)
        atomicAdd(&h[d_topk_e[i]], 1);
    __syncthreads();
    if (t == 0) {
        int off = 0;
        for (int e = 0; e < NE; e++) {
            d_counts[e]  = h[e];
            d_offsets[e] = off;
            off += h[e];
            d_cursor[e] = 0;
        }
    }
}

__global__ void scatter_kernel() {
    int t = blockIdx.x * blockDim.x + threadIdx.x;
    if (t >= T) return;
#pragma unroll
    for (int k = 0; k < TK; k++) {
        int e   = d_topk_e[t * 2 + k];
        int pos = d_offsets[e] + atomicAdd(&d_cursor[e], 1);
        d_slot_token[pos] = t;
        d_slot_w[pos]     = d_topk_w[t * 2 + k];
    }
}

// ===================== A packer (gemm1 input, fp16 m16n8k16 layout) =====================
// Blob per (e, mtile, ktile64): 32 groups (tm*4+tk), tk = k16-step; lane l uint4:
//  {pk2(x[mlo][kb],x[mlo][kb+1]), pk2(x[mhi][kb],..), pk2(x[mlo][kb+8],..), pk2(x[mhi][kb+8],..)}
//  mlo = tm*16+(l>>2), mhi = mlo+8, kb = kt*64 + tk*16 + 2*(l&3).
__global__ __launch_bounds__(256) void pack_x_kernel(const float* __restrict__ x)
{
    int e  = blockIdx.z, mt = blockIdx.y, kt = blockIdx.x;
    int cnt = d_counts[e];
    int m0  = mt * BM;
    if (m0 >= cnt) return;
    int seg = d_offsets[e];

    __shared__ int stok[BM];
    int t = threadIdx.x;
    if (t < BM) {
        int m = m0 + t;
        stok[t] = d_slot_token[seg + (m < cnt ? m : cnt - 1)];
    }
    __syncthreads();

    uint4* dst = d_xp + ((size_t)(e * 16 + mt) * NI1 + kt) * 1024;
#pragma unroll
    for (int i = 0; i < 4; i++) {
        int idx = i * 256 + t;
        int grp = idx >> 5, l = idx & 31;
        int tm = grp >> 2, tk = grp & 3;
        int mlo = tm * 16 + (l >> 2);
        int kb  = kt * 64 + tk * 16 + 2 * (l & 3);
        const float* rlo = x + (size_t)stok[mlo] * H + kb;
        const float* rhi = x + (size_t)stok[mlo + 8] * H + kb;
        float2 p0 = *(const float2*)(rlo);
        float2 p1 = *(const float2*)(rhi);
        float2 p2 = *(const float2*)(rlo + 8);
        float2 p3 = *(const float2*)(rhi + 8);
        dst[idx] = make_uint4(pk2(p0.x, p0.y), pk2(p1.x, p1.y),
                              pk2(p2.x, p2.y), pk2(p3.x, p3.y));
    }
}

// ===================== W packers =====================
// B blob per (e, ntile, ktile64): 32 groups of 512B; lane l uint4 covers 2 k16-steps:
//  {b0(ks=2tkp), b1(2tkp), b0(2tkp+1), b1(2tkp+1)} ; b0 = pk2(w[k][n], w[k+1][n]), b1 = k+8.
// gemm1: group = which*16 + tn*2 + tkp, n = which*FF + nt*64 + tn*8 + (l>>2)
// gemm2: group = tn*2 + tkp,            n = nt*128 + tn*8 + (l>>2)
template <bool IS1>
__global__ __launch_bounds__(256) void pack_w_kernel(const float* __restrict__ W)
{
    constexpr int KTOT = IS1 ? H : FF;
    constexpr int NB   = IS1 ? (2 * FF) : H;
    constexpr int NI   = IS1 ? NI1 : NI2;
    constexpr int NT   = IS1 ? NT1 : NT2;

    int e = blockIdx.z, nt = blockIdx.y, kt = blockIdx.x;
    int t = threadIdx.x;

    uint4* dst = (IS1 ? d_wp1 : d_wp2) + ((size_t)(e * NT + nt) * NI + kt) * 1024;
    const float* Wb = W + (size_t)e * KTOT * NB;

#pragma unroll
    for (int i = 0; i < 4; i++) {
        int idx = i * 256 + t;
        int g2 = idx >> 5, l = idx & 31;
        int tn, tkp, n;
        if (IS1) {
            int which = g2 >> 4, gi = g2 & 15;
            tn = gi >> 1;  tkp = gi & 1;
            n = which * FF + nt * 64 + tn * 8 + (l >> 2);
        } else {
            tn = g2 >> 1;  tkp = g2 & 1;
            n = nt * 128 + tn * 8 + (l >> 2);
        }
        size_t kA = (size_t)(kt * 64 + tkp * 32 + 2 * (l & 3));
        size_t kB = kA + 16;
        dst[idx] = make_uint4(
            pk2(Wb[(kA    ) * NB + n], Wb[(kA + 1) * NB + n]),
            pk2(Wb[(kA + 8) * NB + n], Wb[(kA + 9) * NB + n]),
            pk2(Wb[(kB    ) * NB + n], Wb[(kB + 1) * NB + n]),
            pk2(Wb[(kB + 8) * NB + n], Wb[(kB + 9) * NB + n]));
    }
}

// ===================== GEMM (fp16 m16n8k16, BK=64, 3-stage cp.async) =====================
// IS1: tile 128m x (64 gate | 64 up); warps 4m x 2n; epilogue writes d_ap blob (lane-identity!)
// !IS1: tile 128m x 128n; warps 2m x 4n; epilogue atomicAdd into out[token].
template <int KTOT, bool IS1>
__global__ __launch_bounds__(256, 2)
void moe_gemm_mma(float* __restrict__ out)
{
    constexpr int NI = KTOT / BK;
    constexpr int NT = IS1 ? NT1 : NT2;
    constexpr uint32_t STG = 32768;

    int e   = blockIdx.z;
    int cnt = d_counts[e];
    int m0  = blockIdx.x * BM;
    if (m0 >= cnt) return;
    int seg = d_offsets[e];

    extern __shared__ __align__(16) char smem[];
    uint32_t smem_u = s2u(smem);

    int t = threadIdx.x, w = t >> 5, lane = t & 31;
    int g = lane >> 2, tig = lane & 3;

    const uint4* aBase = (IS1 ? d_xp : d_ap) + ((size_t)(e * 16 + blockIdx.x) * NI) * 1024;
    const uint4* bBase = (IS1 ? d_wp1 : d_wp2) + ((size_t)(e * NT + blockIdx.y) * NI) * 1024;

    constexpr int MT    = IS1 ? 2 : 4;
    constexpr int NSETS = IS1 ? 2 : 1;
    int mw = IS1 ? (w >> 1) : (w >> 2);
    int nw = IS1 ? (w & 1)  : (w & 3);

    uint32_t abase[MT];
#pragma unroll
    for (int mt = 0; mt < MT; mt++)
        abase[mt] = (uint32_t)(((mw * MT + mt) * 4) * 512 + lane * 16);
    uint32_t bbase[NSETS][4];
#pragma unroll
    for (int s = 0; s < NSETS; s++)
#pragma unroll
        for (int nt = 0; nt < 4; nt++) {
            int tn = nw * 4 + nt;
            bbase[s][nt] = (uint32_t)(16384 + (s * 16 + tn * 2) * 512 + lane * 16);
        }

    float acc[NSETS][MT][4][4];
#pragma unroll
    for (int s = 0; s < NSETS; s++)
#pragma unroll
        for (int mt = 0; mt < MT; mt++)
#pragma unroll
            for (int nt = 0; nt < 4; nt++)
#pragma unroll
                for (int q = 0; q < 4; q++) acc[s][mt][nt][q] = 0.f;

    // ---------- prologue: fill stages 0 and 1 ----------
#pragma unroll
    for (int p = 0; p < 2; p++) {
        uint32_t sb = p * STG;
        const char* aSrc = (const char*)(aBase + (size_t)p * 1024);
        const char* bSrc = (const char*)(bBase + (size_t)p * 1024);
#pragma unroll
        for (int i = 0; i < 4; i++) {
            cpa16(smem_u + sb + t * 16 + i * 4096,          aSrc + t * 16 + i * 4096);
            cpa16(smem_u + sb + 16384 + t * 16 + i * 4096,  bSrc + t * 16 + i * 4096);
        }
        cpa_commit();
    }

    // ---------- mainloop ----------
    uint32_t sb = 0;
    for (int it = 0; it < NI; it++) {
        if (it == NI - 1) cpa_wait0(); else cpa_wait1();
        __syncthreads();
        if (it + 2 < NI) {
            uint32_t nb = sb + 2 * STG;
            if (nb >= 3 * STG) nb -= 3 * STG;
            const char* aSrc = (const char*)(aBase + (size_t)(it + 2) * 1024);
            const char* bSrc = (const char*)(bBase + (size_t)(it + 2) * 1024);
#pragma unroll
            for (int i = 0; i < 4; i++) {
                cpa16(smem_u + nb + t * 16 + i * 4096,          aSrc + t * 16 + i * 4096);
                cpa16(smem_u + nb + 16384 + t * 16 + i * 4096,  bSrc + t * 16 + i * 4096);
            }
            cpa_commit();
        }
        const char* sm = smem + sb;
        uint4 bfr[NSETS][4];
#pragma unroll
        for (int ks = 0; ks < 4; ks++) {
            if ((ks & 1) == 0) {
                uint32_t tkpoff = (uint32_t)((ks >> 1) * 512);
#pragma unroll
                for (int s = 0; s < NSETS; s++)
#pragma unroll
                    for (int nt = 0; nt < 4; nt++)
                        bfr[s][nt] = lds128(sm + bbase[s][nt] + tkpoff);
            }
#pragma unroll
            for (int mt = 0; mt < MT; mt++) {
                uint4 af = lds128(sm + abase[mt] + (uint32_t)(ks * 512));
#pragma unroll
                for (int s = 0; s < NSETS; s++)
#pragma unroll
                    for (int nt = 0; nt < 4; nt++) {
                        uint32_t b0 = (ks & 1) ? bfr[s][nt].z : bfr[s][nt].x;
                        uint32_t b1 = (ks & 1) ? bfr[s][nt].w : bfr[s][nt].y;
                        mma_fp16(acc[s][mt][nt], af.x, af.y, af.z, af.w, b0, b1);
                    }
            }
        }
        sb += STG;
        if (sb >= 3 * STG) sb = 0;
    }

    // ---------- epilogue ----------
    if (IS1) {
        // gemm1 n-tile (64 f-cols) == gemm2 k-tile (64 k): kt2 = blockIdx.y.
        // Lane-identity permute: target lane l's fragment = its own acc values.
        uint4* blob = d_ap + ((size_t)(e * 16 + blockIdx.x) * NI2 + blockIdx.y) * 1024;
#pragma unroll
        for (int mt = 0; mt < MT; mt++) {
            int mlo = mw * 32 + mt * 16 + g;
            float wlo = d_slot_w[seg + min(m0 + mlo,     cnt - 1)];
            float whi = d_slot_w[seg + min(m0 + mlo + 8, cnt - 1)];
#pragma unroll
            for (int tb = 0; tb < 2; tb++) {
                int na = tb * 2, nb2 = tb * 2 + 1;
                float l0 = silu(acc[0][mt][na ][0]) * acc[1][mt][na ][0] * wlo;
                float l1 = silu(acc[0][mt][na ][1]) * acc[1][mt][na ][1] * wlo;
                float h0 = silu(acc[0][mt][na ][2]) * acc[1][mt][na ][2] * whi;
                float h1 = silu(acc[0][mt][na ][3]) * acc[1][mt][na ][3] * whi;
                float l2 = silu(acc[0][mt][nb2][0]) * acc[1][mt][nb2][0] * wlo;
                float l3 = silu(acc[0][mt][nb2][1]) * acc[1][mt][nb2][1] * wlo;
                float h2 = silu(acc[0][mt][nb2][2]) * acc[1][mt][nb2][2] * whi;
                float h3 = silu(acc[0][mt][nb2][3]) * acc[1][mt][nb2][3] * whi;
                int grp = (mw * 2 + mt) * 4 + 2 * nw + tb;
                blob[grp * 32 + lane] = make_uint4(pk2(l0, l1), pk2(h0, h1),
                                                   pk2(l2, l3), pk2(h2, h3));
            }
        }
    } else {
        int n0 = blockIdx.y * 128 + nw * 32;
#pragma unroll
        for (int mt = 0; mt < MT; mt++) {
#pragma unroll
            for (int rs = 0; rs < 2; rs++) {
                int m = m0 + mw * 64 + mt * 16 + g + rs * 8;
                if (m < cnt) {
                    int tok = d_slot_token[seg + m];
                    float* row = out + (size_t)tok * H + n0;
#pragma unroll
                    for (int nt = 0; nt < 4; nt++) {
                        atomicAdd(&row[nt * 8 + 2 * tig],     acc[0][mt][nt][rs * 2 + 0]);
                        atomicAdd(&row[nt * 8 + 2 * tig + 1], acc[0][mt][nt][rs * 2 + 1]);
                    }
                }
            }
        }
    }
}

// ===================== launch =====================
extern "C" void kernel_launch(void* const* d_in, const int* in_sizes, int n_in,
                              void* d_out, int out_size)
{
    const float* x   = (const float*)d_in[0];   // [2,1024,1024]
    const float* gw  = (const float*)d_in[1];   // [8,1024]
    const float* wgu = (const float*)d_in[2];   // [8,1024,7168]
    const float* wdn = (const float*)d_in[3];   // [8,3584,1024]
    float* out = (float*)d_out;

    int write_logits = (out_size >= T * H + T * NE) ? 1 : 0;
    float* logits = out + (size_t)T * H;

    cudaFuncSetAttribute(moe_gemm_mma<H, true>,
                         cudaFuncAttributeMaxDynamicSharedMemorySize, SMEMSZ);
    cudaFuncSetAttribute(moe_gemm_mma<FF, false>,
                         cudaFuncAttributeMaxDynamicSharedMemorySize, SMEMSZ);

    zero_out_kernel<<<(T * H + 255) / 256, 256>>>(out);
    router_kernel<<<(T * 32 + 255) / 256, 256>>>(x, gw, logits, write_logits);
    hist_scan_kernel<<<1, 256>>>();
    scatter_kernel<<<(T + 255) / 256, 256>>>();
    pack_w_kernel<true><<<dim3(NI1, NT1, NE), 256>>>(wgu);
    pack_x_kernel<<<dim3(NI1, 16, NE), 256>>>(x);
    moe_gemm_mma<H, true><<<dim3(16, NT1, NE), 256, SMEMSZ>>>(nullptr);  // (16, 56, 8)
    pack_w_kernel<false><<<dim3(NI2, NT2, NE), 256>>>(wdn);
    moe_gemm_mma<FF, false><<<dim3(16, NT2, NE), 256, SMEMSZ>>>(out);    // (16, 8, 8)
}